// round 1
// baseline (speedup 1.0000x reference)
#include <cuda_runtime.h>

#define NN 100000
#define H 128
#define HMID 64
#define OUTC 32
#define NE 1600000
#define NL 3

#define TILE_M 128
#define KK 8
#define AS_LD 132
#define NCHUNK (H / KK)
#define HID_LD 68

// ---------------- scratch (device globals: allocation-free) ----------------
__device__ float g_hu[(size_t)NN * H];
__device__ float g_hi[(size_t)NN * H];
__device__ float g_agg[(size_t)NN * H];
__device__ float g_m[(size_t)NN * H];
__device__ int g_rowptr[2][NN + 1];
__device__ int g_colv[2][NE];
__device__ int g_cnt[2][NN];
__device__ int g_cursor[2][NN];
__device__ int g_bsums[2][256];

__device__ __forceinline__ float* pick(int id) {
    switch (id) {
        case 0: return g_hu;
        case 1: return g_hi;
        case 2: return g_agg;
        default: return g_m;
    }
}

// ---------------- CSR build ----------------
__global__ void k_zero_cnt() {
    int i = blockIdx.x * blockDim.x + threadIdx.x;
    if (i < NN) { g_cnt[0][i] = 0; g_cnt[1][i] = 0; }
}

__global__ void k_hist(const int* __restrict__ dst, int et) {
    int i = blockIdx.x * blockDim.x + threadIdx.x;
    if (i < NE) atomicAdd(&g_cnt[et][dst[i]], 1);
}

__global__ void k_scan1(int et) {
    __shared__ int s[1024];
    int i = blockIdx.x * 1024 + threadIdx.x;
    int v = (i < NN) ? g_cnt[et][i] : 0;
    s[threadIdx.x] = v;
    __syncthreads();
    for (int o = 1; o < 1024; o <<= 1) {
        int t = (threadIdx.x >= (unsigned)o) ? s[threadIdx.x - o] : 0;
        __syncthreads();
        s[threadIdx.x] += t;
        __syncthreads();
    }
    if (i < NN) g_rowptr[et][i + 1] = s[threadIdx.x];
    if (threadIdx.x == 1023) g_bsums[et][blockIdx.x] = s[1023];
    if (i == 0) g_rowptr[et][0] = 0;
}

__global__ void k_scan2(int et, int nb) {
    if (threadIdx.x == 0) {
        int acc = 0;
        for (int i = 0; i < nb; i++) { int t = g_bsums[et][i]; g_bsums[et][i] = acc; acc += t; }
    }
}

__global__ void k_scan3(int et) {
    int i = blockIdx.x * 1024 + threadIdx.x;
    if (i < NN) g_rowptr[et][i + 1] += g_bsums[et][blockIdx.x];
}

__global__ void k_initcur(int et) {
    int i = blockIdx.x * blockDim.x + threadIdx.x;
    if (i < NN) g_cursor[et][i] = g_rowptr[et][i];
}

__global__ void k_fill(const int* __restrict__ src, const int* __restrict__ dst, int et) {
    int i = blockIdx.x * blockDim.x + threadIdx.x;
    if (i < NE) {
        int d = dst[i];
        int p = atomicAdd(&g_cursor[et][d], 1);
        g_colv[et][p] = src[i];
    }
}

// ---------------- mean aggregation (one warp per dst node) ----------------
__global__ void __launch_bounds__(256) k_agg(int hsel, int et) {
    const float* __restrict__ h = pick(hsel);
    int gw = (blockIdx.x * 256 + threadIdx.x) >> 5;
    int lane = threadIdx.x & 31;
    if (gw >= NN) return;
    int beg = g_rowptr[et][gw], end = g_rowptr[et][gw + 1];
    const float4* __restrict__ h4 = (const float4*)h;
    float4 a = make_float4(0.f, 0.f, 0.f, 0.f);
    int e = beg;
    for (; e + 4 <= end; e += 4) {
        int s0 = g_colv[et][e], s1 = g_colv[et][e + 1];
        int s2 = g_colv[et][e + 2], s3 = g_colv[et][e + 3];
        float4 v0 = h4[s0 * 32 + lane];
        float4 v1 = h4[s1 * 32 + lane];
        float4 v2 = h4[s2 * 32 + lane];
        float4 v3 = h4[s3 * 32 + lane];
        a.x += (v0.x + v1.x) + (v2.x + v3.x);
        a.y += (v0.y + v1.y) + (v2.y + v3.y);
        a.z += (v0.z + v1.z) + (v2.z + v3.z);
        a.w += (v0.w + v1.w) + (v2.w + v3.w);
    }
    for (; e < end; e++) {
        int s0 = g_colv[et][e];
        float4 v = h4[s0 * 32 + lane];
        a.x += v.x; a.y += v.y; a.z += v.z; a.w += v.w;
    }
    float invc = 1.0f / fmaxf((float)(end - beg), 1.0f);
    ((float4*)g_agg)[gw * 32 + lane] = make_float4(a.x * invc, a.y * invc, a.z * invc, a.w * invc);
}

// ---------------- main GEMM ----------------
// MODE 0: out = relu(A1@W1 + bias)                               (encoder)
// MODE 1: out = rownorm(A1@W1 + A2@W2 + bias)                    (sage -> m)
// MODE 2: m   = rownorm(A1@W1 + A2@W2 + bias); out=relu(bn(m+out)) (sage + fused h update)
template <int MODE>
__global__ void __launch_bounds__(256) k_gemm(
    const float* __restrict__ A1p, int a1id, int a2id,
    const float* __restrict__ W1, const float* __restrict__ W2,
    const float* __restrict__ bias,
    const float* __restrict__ bng, const float* __restrict__ bnb,
    const float* __restrict__ bnm, const float* __restrict__ bnv,
    float* __restrict__ outp, int outid)
{
    extern __shared__ float sm[];
    const float* A1 = (a1id >= 0) ? pick(a1id) : A1p;
    const float* A2 = (MODE > 0) ? pick(a2id) : nullptr;
    float* out = (outid >= 0) ? pick(outid) : outp;

    float* Ws1 = sm;
    float* Ws2 = sm + H * H;
    float* As1 = sm + ((MODE > 0) ? 2 * H * H : H * H);
    float* As2 = As1 + KK * AS_LD;

    int tid = threadIdx.x;
    int tx = tid & 15, ty = tid >> 4;

    // stage weights into smem (coalesced float4)
    {
        const float4* w = (const float4*)W1;
        float4* d = (float4*)Ws1;
#pragma unroll
        for (int i = 0; i < 16; i++) d[tid + 256 * i] = w[tid + 256 * i];
        if (MODE > 0) {
            const float4* w2 = (const float4*)W2;
            float4* d2 = (float4*)Ws2;
#pragma unroll
            for (int i = 0; i < 16; i++) d2[tid + 256 * i] = w2[tid + 256 * i];
        }
    }

    float acc[8][8];
#pragma unroll
    for (int i = 0; i < 8; i++)
#pragma unroll
        for (int j = 0; j < 8; j++) acc[i][j] = 0.f;

    int rowS = tid >> 1;
    int half = tid & 1;
    int grow = blockIdx.x * TILE_M + rowS;
    if (grow >= NN) grow = NN - 1;
    const float4* gA1 = (const float4*)(A1 + (size_t)grow * H) + half;
    const float4* gA2 = (MODE > 0) ? (const float4*)(A2 + (size_t)grow * H) + half : nullptr;

    float4 p1 = gA1[0];
    float4 p2 = (MODE > 0) ? gA2[0] : make_float4(0.f, 0.f, 0.f, 0.f);
    {
        float t1[4] = {p1.x, p1.y, p1.z, p1.w};
#pragma unroll
        for (int j = 0; j < 4; j++) As1[(half * 4 + j) * AS_LD + rowS] = t1[j];
        if (MODE > 0) {
            float t2[4] = {p2.x, p2.y, p2.z, p2.w};
#pragma unroll
            for (int j = 0; j < 4; j++) As2[(half * 4 + j) * AS_LD + rowS] = t2[j];
        }
    }
    __syncthreads();

#pragma unroll 1
    for (int c = 0; c < NCHUNK; c++) {
        if (c + 1 < NCHUNK) {
            p1 = gA1[(c + 1) * 2];
            if (MODE > 0) p2 = gA2[(c + 1) * 2];
        }
#pragma unroll
        for (int k = 0; k < KK; k++) {
            float4 a0 = *(const float4*)&As1[k * AS_LD + ty * 8];
            float4 a1 = *(const float4*)&As1[k * AS_LD + ty * 8 + 4];
            const float* wr = &Ws1[(c * KK + k) * H + tx * 8];
            float4 w0 = *(const float4*)wr;
            float4 w1 = *(const float4*)(wr + 4);
            float af[8] = {a0.x, a0.y, a0.z, a0.w, a1.x, a1.y, a1.z, a1.w};
            float wf[8] = {w0.x, w0.y, w0.z, w0.w, w1.x, w1.y, w1.z, w1.w};
#pragma unroll
            for (int i = 0; i < 8; i++)
#pragma unroll
                for (int j = 0; j < 8; j++) acc[i][j] = fmaf(af[i], wf[j], acc[i][j]);
            if (MODE > 0) {
                float4 b0 = *(const float4*)&As2[k * AS_LD + ty * 8];
                float4 b1 = *(const float4*)&As2[k * AS_LD + ty * 8 + 4];
                const float* wr2 = &Ws2[(c * KK + k) * H + tx * 8];
                float4 u0 = *(const float4*)wr2;
                float4 u1 = *(const float4*)(wr2 + 4);
                float bf[8] = {b0.x, b0.y, b0.z, b0.w, b1.x, b1.y, b1.z, b1.w};
                float uf[8] = {u0.x, u0.y, u0.z, u0.w, u1.x, u1.y, u1.z, u1.w};
#pragma unroll
                for (int i = 0; i < 8; i++)
#pragma unroll
                    for (int j = 0; j < 8; j++) acc[i][j] = fmaf(bf[i], uf[j], acc[i][j]);
            }
        }
        __syncthreads();
        if (c + 1 < NCHUNK) {
            float t1[4] = {p1.x, p1.y, p1.z, p1.w};
#pragma unroll
            for (int j = 0; j < 4; j++) As1[(half * 4 + j) * AS_LD + rowS] = t1[j];
            if (MODE > 0) {
                float t2[4] = {p2.x, p2.y, p2.z, p2.w};
#pragma unroll
                for (int j = 0; j < 4; j++) As2[(half * 4 + j) * AS_LD + rowS] = t2[j];
            }
            __syncthreads();
        }
    }

    const int c0 = tx * 8;
    const int rbase = blockIdx.x * TILE_M + ty * 8;

    if (MODE == 0) {
#pragma unroll
        for (int i = 0; i < 8; i++) {
            int r = rbase + i;
            if (r < NN) {
                float o[8];
#pragma unroll
                for (int j = 0; j < 8; j++) o[j] = fmaxf(acc[i][j] + bias[c0 + j], 0.f);
                *(float4*)&out[(size_t)r * H + c0]     = make_float4(o[0], o[1], o[2], o[3]);
                *(float4*)&out[(size_t)r * H + c0 + 4] = make_float4(o[4], o[5], o[6], o[7]);
            }
        }
    } else {
        float bv[8];
#pragma unroll
        for (int j = 0; j < 8; j++) bv[j] = bias[c0 + j];
        float scl[8], mh[8], bb[8];
        if (MODE == 2) {
#pragma unroll
            for (int j = 0; j < 8; j++) {
                scl[j] = bng[c0 + j] * rsqrtf(bnv[c0 + j] + 1e-5f);
                mh[j]  = bnm[c0 + j];
                bb[j]  = bnb[c0 + j];
            }
        }
#pragma unroll
        for (int i = 0; i < 8; i++) {
            float ss = 0.f;
#pragma unroll
            for (int j = 0; j < 8; j++) {
                acc[i][j] += bv[j];
                ss = fmaf(acc[i][j], acc[i][j], ss);
            }
            ss += __shfl_xor_sync(0xffffffffu, ss, 8);
            ss += __shfl_xor_sync(0xffffffffu, ss, 4);
            ss += __shfl_xor_sync(0xffffffffu, ss, 2);
            ss += __shfl_xor_sync(0xffffffffu, ss, 1);
            float inv = 1.0f / fmaxf(sqrtf(ss), 1e-12f);
            int r = rbase + i;
            if (MODE == 1) {
                if (r < NN) {
                    float o[8];
#pragma unroll
                    for (int j = 0; j < 8; j++) o[j] = acc[i][j] * inv;
                    *(float4*)&out[(size_t)r * H + c0]     = make_float4(o[0], o[1], o[2], o[3]);
                    *(float4*)&out[(size_t)r * H + c0 + 4] = make_float4(o[4], o[5], o[6], o[7]);
                }
            } else {
                if (r < NN) {
                    float4 h0 = *(const float4*)&out[(size_t)r * H + c0];
                    float4 h1 = *(const float4*)&out[(size_t)r * H + c0 + 4];
                    float hv[8] = {h0.x, h0.y, h0.z, h0.w, h1.x, h1.y, h1.z, h1.w};
                    float o[8];
#pragma unroll
                    for (int j = 0; j < 8; j++) {
                        float t = acc[i][j] * inv + hv[j];
                        o[j] = fmaxf((t - mh[j]) * scl[j] + bb[j], 0.f);
                    }
                    *(float4*)&out[(size_t)r * H + c0]     = make_float4(o[0], o[1], o[2], o[3]);
                    *(float4*)&out[(size_t)r * H + c0 + 4] = make_float4(o[4], o[5], o[6], o[7]);
                }
            }
        }
    }
}

// ---------------- elementwise: h_i = relu(bn(m + h_i)) ----------------
__global__ void k_bnrelu(const float* __restrict__ bng, const float* __restrict__ bnb,
                         const float* __restrict__ bnm, const float* __restrict__ bnv) {
    int i = blockIdx.x * blockDim.x + threadIdx.x;
    if (i >= NN * (H / 4)) return;
    int c0 = (i & 31) * 4;
    float4 hv = ((const float4*)g_hi)[i];
    float4 mv = ((const float4*)g_m)[i];
    float hh[4] = {hv.x, hv.y, hv.z, hv.w};
    float mm[4] = {mv.x, mv.y, mv.z, mv.w};
    float o[4];
#pragma unroll
    for (int j = 0; j < 4; j++) {
        float t = hh[j] + mm[j];
        float s = bng[c0 + j] * rsqrtf(bnv[c0 + j] + 1e-5f);
        o[j] = fmaxf((t - bnm[c0 + j]) * s + bnb[c0 + j], 0.f);
    }
    ((float4*)g_hi)[i] = make_float4(o[0], o[1], o[2], o[3]);
}

// ---------------- classifier: out = relu(h_u@W1+b1)@W2 + b2 ----------------
__global__ void __launch_bounds__(256) k_cls(const float* __restrict__ W1, const float* __restrict__ b1,
                                             const float* __restrict__ W2, const float* __restrict__ b2,
                                             float* __restrict__ out) {
    extern __shared__ float sm[];
    float* W1s = sm;                       // H*HMID
    float* W2s = W1s + H * HMID;           // HMID*OUTC
    float* hid = W2s + HMID * OUTC;        // TILE_M * HID_LD
    float* As1 = hid + TILE_M * HID_LD;    // KK*AS_LD
    const float* A = g_hu;

    int tid = threadIdx.x, tx = tid & 15, ty = tid >> 4;

    {
        const float4* w = (const float4*)W1;
        float4* d = (float4*)W1s;
#pragma unroll
        for (int i = 0; i < 8; i++) d[tid + 256 * i] = w[tid + 256 * i];
        const float4* w2 = (const float4*)W2;
        float4* d2 = (float4*)W2s;
#pragma unroll
        for (int i = 0; i < 2; i++) d2[tid + 256 * i] = w2[tid + 256 * i];
    }

    float acc1[8][4];
#pragma unroll
    for (int i = 0; i < 8; i++)
#pragma unroll
        for (int j = 0; j < 4; j++) acc1[i][j] = 0.f;

    int rowS = tid >> 1, half = tid & 1;
    int grow = blockIdx.x * TILE_M + rowS;
    if (grow >= NN) grow = NN - 1;
    const float4* gA = (const float4*)(A + (size_t)grow * H) + half;
    float4 p1 = gA[0];
    {
        float t[4] = {p1.x, p1.y, p1.z, p1.w};
#pragma unroll
        for (int j = 0; j < 4; j++) As1[(half * 4 + j) * AS_LD + rowS] = t[j];
    }
    __syncthreads();

#pragma unroll 1
    for (int c = 0; c < NCHUNK; c++) {
        if (c + 1 < NCHUNK) p1 = gA[(c + 1) * 2];
#pragma unroll
        for (int k = 0; k < KK; k++) {
            float4 a0 = *(const float4*)&As1[k * AS_LD + ty * 8];
            float4 a1 = *(const float4*)&As1[k * AS_LD + ty * 8 + 4];
            float4 w = *(const float4*)&W1s[(c * KK + k) * HMID + tx * 4];
            float af[8] = {a0.x, a0.y, a0.z, a0.w, a1.x, a1.y, a1.z, a1.w};
            float wf[4] = {w.x, w.y, w.z, w.w};
#pragma unroll
            for (int i = 0; i < 8; i++)
#pragma unroll
                for (int j = 0; j < 4; j++) acc1[i][j] = fmaf(af[i], wf[j], acc1[i][j]);
        }
        __syncthreads();
        if (c + 1 < NCHUNK) {
            float t[4] = {p1.x, p1.y, p1.z, p1.w};
#pragma unroll
            for (int j = 0; j < 4; j++) As1[(half * 4 + j) * AS_LD + rowS] = t[j];
            __syncthreads();
        }
    }

    {
        float b1v[4];
#pragma unroll
        for (int j = 0; j < 4; j++) b1v[j] = b1[tx * 4 + j];
#pragma unroll
        for (int i = 0; i < 8; i++)
#pragma unroll
            for (int j = 0; j < 4; j++)
                hid[(ty * 8 + i) * HID_LD + tx * 4 + j] = fmaxf(acc1[i][j] + b1v[j], 0.f);
    }
    __syncthreads();

    float acc2[8][2];
#pragma unroll
    for (int i = 0; i < 8; i++) { acc2[i][0] = 0.f; acc2[i][1] = 0.f; }
#pragma unroll 8
    for (int k = 0; k < HMID; k++) {
        float w0 = W2s[k * OUTC + tx * 2];
        float w1 = W2s[k * OUTC + tx * 2 + 1];
#pragma unroll
        for (int i = 0; i < 8; i++) {
            float a = hid[(ty * 8 + i) * HID_LD + k];
            acc2[i][0] = fmaf(a, w0, acc2[i][0]);
            acc2[i][1] = fmaf(a, w1, acc2[i][1]);
        }
    }
    float b20 = b2[tx * 2], b21 = b2[tx * 2 + 1];
#pragma unroll
    for (int i = 0; i < 8; i++) {
        int r = blockIdx.x * TILE_M + ty * 8 + i;
        if (r < NN) {
            float2 o = make_float2(acc2[i][0] + b20, acc2[i][1] + b21);
            *(float2*)&out[(size_t)r * OUTC + tx * 2] = o;
        }
    }
}

// ---------------- launch ----------------
extern "C" void kernel_launch(void* const* d_in, const int* in_sizes, int n_in,
                              void* d_out, int out_size) {
    const float* x_user  = (const float*)d_in[0];
    const float* x_item  = (const float*)d_in[1];
    const float* enc_W_u = (const float*)d_in[2];
    const float* enc_b_u = (const float*)d_in[3];
    const float* enc_W_i = (const float*)d_in[4];
    const float* enc_b_i = (const float*)d_in[5];
    const float* Wl_ui = (const float*)d_in[6];
    const float* bl_ui = (const float*)d_in[7];
    const float* Wr_ui = (const float*)d_in[8];
    const float* Wl_iu = (const float*)d_in[9];
    const float* bl_iu = (const float*)d_in[10];
    const float* Wr_iu = (const float*)d_in[11];
    const float* bng_u = (const float*)d_in[12];
    const float* bnb_u = (const float*)d_in[13];
    const float* bnm_u = (const float*)d_in[14];
    const float* bnv_u = (const float*)d_in[15];
    const float* bng_i = (const float*)d_in[16];
    const float* bnb_i = (const float*)d_in[17];
    const float* bnm_i = (const float*)d_in[18];
    const float* bnv_i = (const float*)d_in[19];
    const float* cW1 = (const float*)d_in[20];
    const float* cb1 = (const float*)d_in[21];
    const float* cW2 = (const float*)d_in[22];
    const float* cb2 = (const float*)d_in[23];
    const int* ei_ui = (const int*)d_in[24];
    const int* ei_iu = (const int*)d_in[25];
    float* outp = (float*)d_out;

    const int SMEM_ENC  = (H * H + KK * AS_LD) * 4;                    // 69760
    const int SMEM_SAGE = (2 * H * H + 2 * KK * AS_LD) * 4;            // 139520
    const int SMEM_CLS  = (H * HMID + HMID * OUTC + TILE_M * HID_LD + KK * AS_LD) * 4; // 80000

    cudaFuncSetAttribute(k_gemm<0>, cudaFuncAttributeMaxDynamicSharedMemorySize, SMEM_ENC);
    cudaFuncSetAttribute(k_gemm<1>, cudaFuncAttributeMaxDynamicSharedMemorySize, SMEM_SAGE);
    cudaFuncSetAttribute(k_gemm<2>, cudaFuncAttributeMaxDynamicSharedMemorySize, SMEM_SAGE);
    cudaFuncSetAttribute(k_cls,     cudaFuncAttributeMaxDynamicSharedMemorySize, SMEM_CLS);

    const int GEMM_GRID = (NN + TILE_M - 1) / TILE_M;   // 782
    const int EB = (NE + 255) / 256;                    // 6250
    const int NB = (NN + 255) / 256;                    // 391
    const int SB = (NN + 1023) / 1024;                  // 98

    // CSR build for both edge types (src = ei[0,:], dst = ei[1,:])
    k_zero_cnt<<<NB, 256>>>();
    k_hist<<<EB, 256>>>(ei_ui + NE, 0);
    k_hist<<<EB, 256>>>(ei_iu + NE, 1);
    k_scan1<<<SB, 1024>>>(0); k_scan2<<<1, 32>>>(0, SB); k_scan3<<<SB, 1024>>>(0);
    k_scan1<<<SB, 1024>>>(1); k_scan2<<<1, 32>>>(1, SB); k_scan3<<<SB, 1024>>>(1);
    k_initcur<<<NB, 256>>>(0);
    k_initcur<<<NB, 256>>>(1);
    k_fill<<<EB, 256>>>(ei_ui, ei_ui + NE, 0);
    k_fill<<<EB, 256>>>(ei_iu, ei_iu + NE, 1);

    // encoders: h_u = relu(x_u@W+b), h_i = relu(x_i@W+b)
    k_gemm<0><<<GEMM_GRID, 256, SMEM_ENC>>>(x_user, -1, -1, enc_W_u, nullptr, enc_b_u,
                                            nullptr, nullptr, nullptr, nullptr, nullptr, 0);
    k_gemm<0><<<GEMM_GRID, 256, SMEM_ENC>>>(x_item, -1, -1, enc_W_i, nullptr, enc_b_i,
                                            nullptr, nullptr, nullptr, nullptr, nullptr, 1);

    for (int l = 0; l < NL; l++) {
        const float* wl_ui = Wl_ui + (size_t)l * H * H;
        const float* wr_ui = Wr_ui + (size_t)l * H * H;
        const float* b_ui  = bl_ui + (size_t)l * H;
        const float* wl_iu = Wl_iu + (size_t)l * H * H;
        const float* wr_iu = Wr_iu + (size_t)l * H * H;
        const float* b_iu  = bl_iu + (size_t)l * H;

        // m_item = rownorm(mean_ui(h_u)@Wl_ui + h_u@Wr_ui + b) -> g_m
        k_agg<<<NN / 8, 256>>>(0, 0);
        k_gemm<1><<<GEMM_GRID, 256, SMEM_SAGE>>>(nullptr, 2, 0, wl_ui, wr_ui, b_ui,
                                                 nullptr, nullptr, nullptr, nullptr, nullptr, 3);
        // m_user = rownorm(mean_iu(h_i)@Wl_iu + h_i@Wr_iu + b); h_u = relu(bn(m_user + h_u))
        k_agg<<<NN / 8, 256>>>(1, 1);
        k_gemm<2><<<GEMM_GRID, 256, SMEM_SAGE>>>(nullptr, 2, 1, wl_iu, wr_iu, b_iu,
                                                 bng_u + (size_t)l * H, bnb_u + (size_t)l * H,
                                                 bnm_u + (size_t)l * H, bnv_u + (size_t)l * H,
                                                 nullptr, 0);
        // h_i = relu(bn(m_item + h_i))
        k_bnrelu<<<(NN * (H / 4) + 255) / 256, 256>>>(bng_i + (size_t)l * H, bnb_i + (size_t)l * H,
                                                      bnm_i + (size_t)l * H, bnv_i + (size_t)l * H);
    }

    k_cls<<<GEMM_GRID, 256, SMEM_CLS>>>(cW1, cb1, cW2, cb2, outp);
}

// round 2
// speedup vs baseline: 1.6920x; 1.6920x over previous
#include <cuda_runtime.h>
#include <cstdint>

#define NN 100000
#define H 128
#define HMID 64
#define OUTC 32
#define NE 1600000
#define NL 3

#define TILE_M 128
#define KK 8
#define AS_LD 132
#define NCHUNK (H / KK)
#define HID_LD 68

#define WLD 136
#define ALD 36

// ---------------- scratch (device globals: allocation-free) ----------------
__device__ float g_hu[(size_t)NN * H];
__device__ float g_hi[(size_t)NN * H];
__device__ float g_agg[(size_t)NN * H];
__device__ float g_m[(size_t)NN * H];
__device__ int g_rowptr[2][NN + 1];
__device__ int g_colv[2][NE];
__device__ int g_cnt[2][NN];
__device__ int g_cursor[2][NN];
__device__ int g_bsums[2][256];

__device__ __forceinline__ float* pick(int id) {
    switch (id) {
        case 0: return g_hu;
        case 1: return g_hi;
        case 2: return g_agg;
        default: return g_m;
    }
}

__device__ __forceinline__ float to_tf32(float x) {
    uint32_t u;
    asm("cvt.rna.tf32.f32 %0, %1;" : "=r"(u) : "f"(x));
    return __uint_as_float(u);
}

__device__ __forceinline__ void mma_tf32(float c[4], const uint32_t a[4], const uint32_t b[2]) {
    asm volatile(
        "mma.sync.aligned.m16n8k8.row.col.f32.tf32.tf32.f32 "
        "{%0,%1,%2,%3}, {%4,%5,%6,%7}, {%8,%9}, {%0,%1,%2,%3};"
        : "+f"(c[0]), "+f"(c[1]), "+f"(c[2]), "+f"(c[3])
        : "r"(a[0]), "r"(a[1]), "r"(a[2]), "r"(a[3]), "r"(b[0]), "r"(b[1]));
}

// ---------------- CSR build ----------------
__global__ void k_zero_cnt() {
    int i = blockIdx.x * blockDim.x + threadIdx.x;
    if (i < NN) { g_cnt[0][i] = 0; g_cnt[1][i] = 0; }
}

__global__ void k_hist(const int* __restrict__ dst, int et) {
    int i = blockIdx.x * blockDim.x + threadIdx.x;
    if (i < NE) atomicAdd(&g_cnt[et][dst[i]], 1);
}

__global__ void k_scan1(int et) {
    __shared__ int s[1024];
    int i = blockIdx.x * 1024 + threadIdx.x;
    int v = (i < NN) ? g_cnt[et][i] : 0;
    s[threadIdx.x] = v;
    __syncthreads();
    for (int o = 1; o < 1024; o <<= 1) {
        int t = (threadIdx.x >= (unsigned)o) ? s[threadIdx.x - o] : 0;
        __syncthreads();
        s[threadIdx.x] += t;
        __syncthreads();
    }
    if (i < NN) g_rowptr[et][i + 1] = s[threadIdx.x];
    if (threadIdx.x == 1023) g_bsums[et][blockIdx.x] = s[1023];
    if (i == 0) g_rowptr[et][0] = 0;
}

__global__ void k_scan2(int et, int nb) {
    if (threadIdx.x == 0) {
        int acc = 0;
        for (int i = 0; i < nb; i++) { int t = g_bsums[et][i]; g_bsums[et][i] = acc; acc += t; }
    }
}

__global__ void k_scan3(int et) {
    int i = blockIdx.x * 1024 + threadIdx.x;
    if (i < NN) g_rowptr[et][i + 1] += g_bsums[et][blockIdx.x];
}

__global__ void k_initcur(int et) {
    int i = blockIdx.x * blockDim.x + threadIdx.x;
    if (i < NN) g_cursor[et][i] = g_rowptr[et][i];
}

__global__ void k_fill(const int* __restrict__ src, const int* __restrict__ dst, int et) {
    int i = blockIdx.x * blockDim.x + threadIdx.x;
    if (i < NE) {
        int d = dst[i];
        int p = atomicAdd(&g_cursor[et][d], 1);
        g_colv[et][p] = src[i];
    }
}

// ---------------- mean aggregation (one warp per dst node) ----------------
__global__ void __launch_bounds__(256) k_agg(int hsel, int et) {
    const float* __restrict__ h = pick(hsel);
    int gw = (blockIdx.x * 256 + threadIdx.x) >> 5;
    int lane = threadIdx.x & 31;
    if (gw >= NN) return;
    int beg = g_rowptr[et][gw], end = g_rowptr[et][gw + 1];
    const float4* __restrict__ h4 = (const float4*)h;
    float4 a = make_float4(0.f, 0.f, 0.f, 0.f);
    int e = beg;
    for (; e + 4 <= end; e += 4) {
        int s0 = g_colv[et][e], s1 = g_colv[et][e + 1];
        int s2 = g_colv[et][e + 2], s3 = g_colv[et][e + 3];
        float4 v0 = h4[s0 * 32 + lane];
        float4 v1 = h4[s1 * 32 + lane];
        float4 v2 = h4[s2 * 32 + lane];
        float4 v3 = h4[s3 * 32 + lane];
        a.x += (v0.x + v1.x) + (v2.x + v3.x);
        a.y += (v0.y + v1.y) + (v2.y + v3.y);
        a.z += (v0.z + v1.z) + (v2.z + v3.z);
        a.w += (v0.w + v1.w) + (v2.w + v3.w);
    }
    for (; e < end; e++) {
        int s0 = g_colv[et][e];
        float4 v = h4[s0 * 32 + lane];
        a.x += v.x; a.y += v.y; a.z += v.z; a.w += v.w;
    }
    float invc = 1.0f / fmaxf((float)(end - beg), 1.0f);
    ((float4*)g_agg)[gw * 32 + lane] = make_float4(a.x * invc, a.y * invc, a.z * invc, a.w * invc);
}

// ---------------- tensor-core GEMM (tf32 mma) ----------------
// MODE 0: out = relu(A1@W1 + bias)                                (encoder, K=128)
// MODE 1: out = rownorm(A1@W1 + A2@W2 + bias)                     (sage -> m, K=256 virt)
// MODE 2: m = rownorm(A1@W1 + A2@W2 + bias); out = relu(bn(m+out)) (sage + fused h update)
template <int MODE>
__global__ void __launch_bounds__(256) k_gemm_tc(
    const float* __restrict__ A1p, int a1id, int a2id,
    const float* __restrict__ W1, const float* __restrict__ W2,
    const float* __restrict__ bias,
    const float* __restrict__ bng, const float* __restrict__ bnb,
    const float* __restrict__ bnm, const float* __restrict__ bnv,
    float* __restrict__ outp, int outid)
{
    extern __shared__ float sm[];
    const int NST = (MODE == 0) ? 4 : 8;      // 32-wide k stripes; virtual K = NST*32
    float* Ws  = sm;                          // [NST*32][WLD]
    float* As  = Ws + NST * 32 * WLD;         // [128][ALD]
    float* red = As + 128 * ALD;              // [128][2]

    const float* A1 = (a1id >= 0) ? pick(a1id) : A1p;
    const float* A2 = (MODE > 0) ? pick(a2id) : nullptr;
    float* out = (outid >= 0) ? pick(outid) : outp;

    int tid = threadIdx.x;
    int lane = tid & 31, w = tid >> 5;
    int wm = w & 3, wn = w >> 2;      // 4 warps in M, 2 in N
    int p = lane >> 2, q = lane & 3;

    // stage W (tf32-converted) into smem, [k][n] row-major with pad WLD
#pragma unroll
    for (int j = 0; j < ((MODE == 0) ? 16 : 32); j++) {
        int i = tid + 256 * j;               // float4 index over NST*32 x 128
        int row = i >> 5;
        int c4 = (i & 31) << 2;
        const float* src = (MODE > 0 && row >= 128) ? (W2 + (size_t)(row - 128) * H)
                                                    : (W1 + (size_t)row * H);
        float4 v = *(const float4*)(src + c4);
        float* d = &Ws[row * WLD + c4];
        d[0] = to_tf32(v.x); d[1] = to_tf32(v.y); d[2] = to_tf32(v.z); d[3] = to_tf32(v.w);
    }

    float acc[2][8][4];
#pragma unroll
    for (int mt = 0; mt < 2; mt++)
#pragma unroll
        for (int nt = 0; nt < 8; nt++)
#pragma unroll
            for (int e = 0; e < 4; e++) acc[mt][nt][e] = 0.f;

    int rowbase = blockIdx.x * TILE_M;
    int arow = tid >> 3;                 // 0..31 (+32 per j)
    int ac4 = (tid & 7) << 2;            // 0..28
    int garow[4];
#pragma unroll
    for (int j = 0; j < 4; j++) {
        int r = rowbase + arow + 32 * j;
        garow[j] = (r < NN) ? r : (NN - 1);
    }

    float4 pf[4];
#pragma unroll
    for (int j = 0; j < 4; j++)
        pf[j] = *(const float4*)&A1[(size_t)garow[j] * H + ac4];

#pragma unroll 1
    for (int s = 0; s < NST; s++) {
        __syncthreads();
#pragma unroll
        for (int j = 0; j < 4; j++) {
            float* d = &As[(arow + 32 * j) * ALD + ac4];
            d[0] = to_tf32(pf[j].x); d[1] = to_tf32(pf[j].y);
            d[2] = to_tf32(pf[j].z); d[3] = to_tf32(pf[j].w);
        }
        __syncthreads();
        if (s + 1 < NST) {
            const float* Asrc = (MODE > 0 && (s + 1) >= 4) ? A2 : A1;
            int ks = ((s + 1) & 3) * 32;
#pragma unroll
            for (int j = 0; j < 4; j++)
                pf[j] = *(const float4*)&Asrc[(size_t)garow[j] * H + ks + ac4];
        }
#pragma unroll
        for (int cc = 0; cc < 4; cc++) {
            int kl = cc * 8;
            int kg = s * 32 + kl;
            uint32_t a[2][4];
#pragma unroll
            for (int mt = 0; mt < 2; mt++) {
                int r = wm * 32 + mt * 16 + p;
                a[mt][0] = __float_as_uint(As[r * ALD + kl + q]);
                a[mt][1] = __float_as_uint(As[(r + 8) * ALD + kl + q]);
                a[mt][2] = __float_as_uint(As[r * ALD + kl + q + 4]);
                a[mt][3] = __float_as_uint(As[(r + 8) * ALD + kl + q + 4]);
            }
            uint32_t b[8][2];
#pragma unroll
            for (int nt = 0; nt < 8; nt++) {
                int c = wn * 64 + nt * 8 + p;
                b[nt][0] = __float_as_uint(Ws[(kg + q) * WLD + c]);
                b[nt][1] = __float_as_uint(Ws[(kg + q + 4) * WLD + c]);
            }
#pragma unroll
            for (int mt = 0; mt < 2; mt++)
#pragma unroll
                for (int nt = 0; nt < 8; nt++)
                    mma_tf32(acc[mt][nt], a[mt], b[nt]);
        }
    }

    // ---------------- epilogue ----------------
    // acc[mt][nt]: c0:(row p, col 2q) c1:(p,2q+1) c2:(p+8,2q) c3:(p+8,2q+1)
    float bv[8][2];
#pragma unroll
    for (int nt = 0; nt < 8; nt++) {
        int c = wn * 64 + nt * 8 + 2 * q;
        bv[nt][0] = __ldg(&bias[c]);
        bv[nt][1] = __ldg(&bias[c + 1]);
    }
#pragma unroll
    for (int mt = 0; mt < 2; mt++)
#pragma unroll
        for (int nt = 0; nt < 8; nt++) {
            acc[mt][nt][0] += bv[nt][0];
            acc[mt][nt][1] += bv[nt][1];
            acc[mt][nt][2] += bv[nt][0];
            acc[mt][nt][3] += bv[nt][1];
        }

    if (MODE == 0) {
#pragma unroll
        for (int mt = 0; mt < 2; mt++)
#pragma unroll
            for (int rs = 0; rs < 2; rs++) {
                int r = rowbase + wm * 32 + mt * 16 + p + rs * 8;
                if (r < NN) {
#pragma unroll
                    for (int nt = 0; nt < 8; nt++) {
                        int c = wn * 64 + nt * 8 + 2 * q;
                        float2 o = make_float2(fmaxf(acc[mt][nt][rs * 2], 0.f),
                                               fmaxf(acc[mt][nt][rs * 2 + 1], 0.f));
                        *(float2*)&out[(size_t)r * H + c] = o;
                    }
                }
            }
    } else {
        float ss[2][2];
#pragma unroll
        for (int mt = 0; mt < 2; mt++) {
            ss[mt][0] = 0.f; ss[mt][1] = 0.f;
#pragma unroll
            for (int nt = 0; nt < 8; nt++) {
                ss[mt][0] = fmaf(acc[mt][nt][0], acc[mt][nt][0],
                            fmaf(acc[mt][nt][1], acc[mt][nt][1], ss[mt][0]));
                ss[mt][1] = fmaf(acc[mt][nt][2], acc[mt][nt][2],
                            fmaf(acc[mt][nt][3], acc[mt][nt][3], ss[mt][1]));
            }
#pragma unroll
            for (int rs = 0; rs < 2; rs++) {
                ss[mt][rs] += __shfl_xor_sync(0xffffffffu, ss[mt][rs], 1);
                ss[mt][rs] += __shfl_xor_sync(0xffffffffu, ss[mt][rs], 2);
            }
        }
        if (q == 0) {
#pragma unroll
            for (int mt = 0; mt < 2; mt++) {
                red[(wm * 32 + mt * 16 + p) * 2 + wn]     = ss[mt][0];
                red[(wm * 32 + mt * 16 + p + 8) * 2 + wn] = ss[mt][1];
            }
        }
        __syncthreads();

        float scl[8][2], mh[8][2], bb[8][2];
        if (MODE == 2) {
#pragma unroll
            for (int nt = 0; nt < 8; nt++) {
                int c = wn * 64 + nt * 8 + 2 * q;
                scl[nt][0] = __ldg(&bng[c])     * rsqrtf(__ldg(&bnv[c]) + 1e-5f);
                scl[nt][1] = __ldg(&bng[c + 1]) * rsqrtf(__ldg(&bnv[c + 1]) + 1e-5f);
                mh[nt][0] = __ldg(&bnm[c]);     mh[nt][1] = __ldg(&bnm[c + 1]);
                bb[nt][0] = __ldg(&bnb[c]);     bb[nt][1] = __ldg(&bnb[c + 1]);
            }
        }
#pragma unroll
        for (int mt = 0; mt < 2; mt++)
#pragma unroll
            for (int rs = 0; rs < 2; rs++) {
                int lr = wm * 32 + mt * 16 + p + rs * 8;
                float tot = red[lr * 2] + red[lr * 2 + 1];
                float inv = 1.0f / fmaxf(sqrtf(tot), 1e-12f);
                int r = rowbase + lr;
                if (r < NN) {
                    if (MODE == 1) {
#pragma unroll
                        for (int nt = 0; nt < 8; nt++) {
                            int c = wn * 64 + nt * 8 + 2 * q;
                            float2 o = make_float2(acc[mt][nt][rs * 2] * inv,
                                                   acc[mt][nt][rs * 2 + 1] * inv);
                            *(float2*)&out[(size_t)r * H + c] = o;
                        }
                    } else {
#pragma unroll
                        for (int nt = 0; nt < 8; nt++) {
                            int c = wn * 64 + nt * 8 + 2 * q;
                            float2 h = *(const float2*)&out[(size_t)r * H + c];
                            float t0 = fmaf(acc[mt][nt][rs * 2], inv, h.x);
                            float t1 = fmaf(acc[mt][nt][rs * 2 + 1], inv, h.y);
                            float2 o = make_float2(
                                fmaxf(fmaf(t0 - mh[nt][0], scl[nt][0], bb[nt][0]), 0.f),
                                fmaxf(fmaf(t1 - mh[nt][1], scl[nt][1], bb[nt][1]), 0.f));
                            *(float2*)&out[(size_t)r * H + c] = o;
                        }
                    }
                }
            }
    }
}

// ---------------- elementwise: h_i = relu(bn(m + h_i)) ----------------
__global__ void k_bnrelu(const float* __restrict__ bng, const float* __restrict__ bnb,
                         const float* __restrict__ bnm, const float* __restrict__ bnv) {
    int i = blockIdx.x * blockDim.x + threadIdx.x;
    if (i >= NN * (H / 4)) return;
    int c0 = (i & 31) * 4;
    float4 hv = ((const float4*)g_hi)[i];
    float4 mv = ((const float4*)g_m)[i];
    float hh[4] = {hv.x, hv.y, hv.z, hv.w};
    float mm[4] = {mv.x, mv.y, mv.z, mv.w};
    float o[4];
#pragma unroll
    for (int j = 0; j < 4; j++) {
        float t = hh[j] + mm[j];
        float s = bng[c0 + j] * rsqrtf(bnv[c0 + j] + 1e-5f);
        o[j] = fmaxf((t - bnm[c0 + j]) * s + bnb[c0 + j], 0.f);
    }
    ((float4*)g_hi)[i] = make_float4(o[0], o[1], o[2], o[3]);
}

// ---------------- classifier: out = relu(h_u@W1+b1)@W2 + b2 ----------------
__global__ void __launch_bounds__(256) k_cls(const float* __restrict__ W1, const float* __restrict__ b1,
                                             const float* __restrict__ W2, const float* __restrict__ b2,
                                             float* __restrict__ out) {
    extern __shared__ float sm[];
    float* W1s = sm;                       // H*HMID
    float* W2s = W1s + H * HMID;           // HMID*OUTC
    float* hid = W2s + HMID * OUTC;        // TILE_M * HID_LD
    float* As1 = hid + TILE_M * HID_LD;    // KK*AS_LD
    const float* A = g_hu;

    int tid = threadIdx.x, tx = tid & 15, ty = tid >> 4;

    {
        const float4* w = (const float4*)W1;
        float4* d = (float4*)W1s;
#pragma unroll
        for (int i = 0; i < 8; i++) d[tid + 256 * i] = w[tid + 256 * i];
        const float4* w2 = (const float4*)W2;
        float4* d2 = (float4*)W2s;
#pragma unroll
        for (int i = 0; i < 2; i++) d2[tid + 256 * i] = w2[tid + 256 * i];
    }

    float acc1[8][4];
#pragma unroll
    for (int i = 0; i < 8; i++)
#pragma unroll
        for (int j = 0; j < 4; j++) acc1[i][j] = 0.f;

    int rowS = tid >> 1, half = tid & 1;
    int grow = blockIdx.x * TILE_M + rowS;
    if (grow >= NN) grow = NN - 1;
    const float4* gA = (const float4*)(A + (size_t)grow * H) + half;
    float4 p1 = gA[0];
    {
        float t[4] = {p1.x, p1.y, p1.z, p1.w};
#pragma unroll
        for (int j = 0; j < 4; j++) As1[(half * 4 + j) * AS_LD + rowS] = t[j];
    }
    __syncthreads();

#pragma unroll 1
    for (int c = 0; c < NCHUNK; c++) {
        if (c + 1 < NCHUNK) p1 = gA[(c + 1) * 2];
#pragma unroll
        for (int k = 0; k < KK; k++) {
            float4 a0 = *(const float4*)&As1[k * AS_LD + ty * 8];
            float4 a1 = *(const float4*)&As1[k * AS_LD + ty * 8 + 4];
            float4 w = *(const float4*)&W1s[(c * KK + k) * HMID + tx * 4];
            float af[8] = {a0.x, a0.y, a0.z, a0.w, a1.x, a1.y, a1.z, a1.w};
            float wf[4] = {w.x, w.y, w.z, w.w};
#pragma unroll
            for (int i = 0; i < 8; i++)
#pragma unroll
                for (int j = 0; j < 4; j++) acc1[i][j] = fmaf(af[i], wf[j], acc1[i][j]);
        }
        __syncthreads();
        if (c + 1 < NCHUNK) {
            float t[4] = {p1.x, p1.y, p1.z, p1.w};
#pragma unroll
            for (int j = 0; j < 4; j++) As1[(half * 4 + j) * AS_LD + rowS] = t[j];
            __syncthreads();
        }
    }

    {
        float b1v[4];
#pragma unroll
        for (int j = 0; j < 4; j++) b1v[j] = b1[tx * 4 + j];
#pragma unroll
        for (int i = 0; i < 8; i++)
#pragma unroll
            for (int j = 0; j < 4; j++)
                hid[(ty * 8 + i) * HID_LD + tx * 4 + j] = fmaxf(acc1[i][j] + b1v[j], 0.f);
    }
    __syncthreads();

    float acc2[8][2];
#pragma unroll
    for (int i = 0; i < 8; i++) { acc2[i][0] = 0.f; acc2[i][1] = 0.f; }
#pragma unroll 8
    for (int k = 0; k < HMID; k++) {
        float w0 = W2s[k * OUTC + tx * 2];
        float w1 = W2s[k * OUTC + tx * 2 + 1];
#pragma unroll
        for (int i = 0; i < 8; i++) {
            float a = hid[(ty * 8 + i) * HID_LD + k];
            acc2[i][0] = fmaf(a, w0, acc2[i][0]);
            acc2[i][1] = fmaf(a, w1, acc2[i][1]);
        }
    }
    float b20 = b2[tx * 2], b21 = b2[tx * 2 + 1];
#pragma unroll
    for (int i = 0; i < 8; i++) {
        int r = blockIdx.x * TILE_M + ty * 8 + i;
        if (r < NN) {
            float2 o = make_float2(acc2[i][0] + b20, acc2[i][1] + b21);
            *(float2*)&out[(size_t)r * OUTC + tx * 2] = o;
        }
    }
}

// ---------------- launch ----------------
extern "C" void kernel_launch(void* const* d_in, const int* in_sizes, int n_in,
                              void* d_out, int out_size) {
    const float* x_user  = (const float*)d_in[0];
    const float* x_item  = (const float*)d_in[1];
    const float* enc_W_u = (const float*)d_in[2];
    const float* enc_b_u = (const float*)d_in[3];
    const float* enc_W_i = (const float*)d_in[4];
    const float* enc_b_i = (const float*)d_in[5];
    const float* Wl_ui = (const float*)d_in[6];
    const float* bl_ui = (const float*)d_in[7];
    const float* Wr_ui = (const float*)d_in[8];
    const float* Wl_iu = (const float*)d_in[9];
    const float* bl_iu = (const float*)d_in[10];
    const float* Wr_iu = (const float*)d_in[11];
    const float* bng_u = (const float*)d_in[12];
    const float* bnb_u = (const float*)d_in[13];
    const float* bnm_u = (const float*)d_in[14];
    const float* bnv_u = (const float*)d_in[15];
    const float* bng_i = (const float*)d_in[16];
    const float* bnb_i = (const float*)d_in[17];
    const float* bnm_i = (const float*)d_in[18];
    const float* bnv_i = (const float*)d_in[19];
    const float* cW1 = (const float*)d_in[20];
    const float* cb1 = (const float*)d_in[21];
    const float* cW2 = (const float*)d_in[22];
    const float* cb2 = (const float*)d_in[23];
    const int* ei_ui = (const int*)d_in[24];
    const int* ei_iu = (const int*)d_in[25];
    float* outp = (float*)d_out;

    const int SMEM_TC0  = (4 * 32 * WLD + 128 * ALD + 256) * 4;   // 89,088
    const int SMEM_TC12 = (8 * 32 * WLD + 128 * ALD + 256) * 4;   // 158,720
    const int SMEM_CLS  = (H * HMID + HMID * OUTC + TILE_M * HID_LD + KK * AS_LD) * 4;

    cudaFuncSetAttribute(k_gemm_tc<0>, cudaFuncAttributeMaxDynamicSharedMemorySize, SMEM_TC0);
    cudaFuncSetAttribute(k_gemm_tc<1>, cudaFuncAttributeMaxDynamicSharedMemorySize, SMEM_TC12);
    cudaFuncSetAttribute(k_gemm_tc<2>, cudaFuncAttributeMaxDynamicSharedMemorySize, SMEM_TC12);
    cudaFuncSetAttribute(k_cls,        cudaFuncAttributeMaxDynamicSharedMemorySize, SMEM_CLS);

    const int GEMM_GRID = (NN + TILE_M - 1) / TILE_M;   // 782
    const int EB = (NE + 255) / 256;                    // 6250
    const int NB = (NN + 255) / 256;                    // 391
    const int SB = (NN + 1023) / 1024;                  // 98

    // CSR build for both edge types (src = ei[0,:], dst = ei[1,:])
    k_zero_cnt<<<NB, 256>>>();
    k_hist<<<EB, 256>>>(ei_ui + NE, 0);
    k_hist<<<EB, 256>>>(ei_iu + NE, 1);
    k_scan1<<<SB, 1024>>>(0); k_scan2<<<1, 32>>>(0, SB); k_scan3<<<SB, 1024>>>(0);
    k_scan1<<<SB, 1024>>>(1); k_scan2<<<1, 32>>>(1, SB); k_scan3<<<SB, 1024>>>(1);
    k_initcur<<<NB, 256>>>(0);
    k_initcur<<<NB, 256>>>(1);
    k_fill<<<EB, 256>>>(ei_ui, ei_ui + NE, 0);
    k_fill<<<EB, 256>>>(ei_iu, ei_iu + NE, 1);

    // encoders: h_u = relu(x_u@W+b), h_i = relu(x_i@W+b)
    k_gemm_tc<0><<<GEMM_GRID, 256, SMEM_TC0>>>(x_user, -1, -1, enc_W_u, nullptr, enc_b_u,
                                               nullptr, nullptr, nullptr, nullptr, nullptr, 0);
    k_gemm_tc<0><<<GEMM_GRID, 256, SMEM_TC0>>>(x_item, -1, -1, enc_W_i, nullptr, enc_b_i,
                                               nullptr, nullptr, nullptr, nullptr, nullptr, 1);

    for (int l = 0; l < NL; l++) {
        const float* wl_ui = Wl_ui + (size_t)l * H * H;
        const float* wr_ui = Wr_ui + (size_t)l * H * H;
        const float* b_ui  = bl_ui + (size_t)l * H;
        const float* wl_iu = Wl_iu + (size_t)l * H * H;
        const float* wr_iu = Wr_iu + (size_t)l * H * H;
        const float* b_iu  = bl_iu + (size_t)l * H;

        // m_item = rownorm(mean_ui(h_u)@Wl_ui + h_u@Wr_ui + b) -> g_m
        k_agg<<<NN / 8, 256>>>(0, 0);
        k_gemm_tc<1><<<GEMM_GRID, 256, SMEM_TC12>>>(nullptr, 2, 0, wl_ui, wr_ui, b_ui,
                                                    nullptr, nullptr, nullptr, nullptr, nullptr, 3);
        // m_user = rownorm(mean_iu(h_i)@Wl_iu + h_i@Wr_iu + b); h_u = relu(bn(m_user + h_u))
        k_agg<<<NN / 8, 256>>>(1, 1);
        k_gemm_tc<2><<<GEMM_GRID, 256, SMEM_TC12>>>(nullptr, 2, 1, wl_iu, wr_iu, b_iu,
                                                    bng_u + (size_t)l * H, bnb_u + (size_t)l * H,
                                                    bnm_u + (size_t)l * H, bnv_u + (size_t)l * H,
                                                    nullptr, 0);
        // h_i = relu(bn(m_item + h_i))
        k_bnrelu<<<(NN * (H / 4) + 255) / 256, 256>>>(bng_i + (size_t)l * H, bnb_i + (size_t)l * H,
                                                      bnm_i + (size_t)l * H, bnv_i + (size_t)l * H);
    }

    k_cls<<<GEMM_GRID, 256, SMEM_CLS>>>(cW1, cb1, cW2, cb2, outp);
}

// round 4
// speedup vs baseline: 2.1926x; 1.2959x over previous
#include <cuda_runtime.h>
#include <cstdint>

#define NN 100000
#define H 128
#define NE 1600000
#define NL 3
#define OUTC 32
#define HMID 64

#define TILE_M 128
#define ALD 36

// ---------------- scratch: one big device global, 6 logical buffers ----------------
// 0=hu0 1=hu1 2=hi0 3=hi1 4=aggA(ui, also cls-hid scratch) 5=aggB(iu)
__device__ float g_big[(size_t)6 * NN * H];
__device__ int g_rowptr[2][NN + 1];
__device__ int g_colv[2][NE];
__device__ int g_cnt[2][NN];
__device__ int g_cursor[2][NN];
__device__ int g_bsums[2][256];

__device__ __forceinline__ float* pick(int id) {
    return g_big + (size_t)id * NN * H;
}

__device__ __forceinline__ uint32_t to_tf32_u(float x) {
    uint32_t u;
    asm("cvt.rna.tf32.f32 %0, %1;" : "=r"(u) : "f"(x));
    return u;
}

__device__ __forceinline__ void mma_tf32(float c[4], const uint32_t a[4], const uint32_t b[2]) {
    asm volatile(
        "mma.sync.aligned.m16n8k8.row.col.f32.tf32.tf32.f32 "
        "{%0,%1,%2,%3}, {%4,%5,%6,%7}, {%8,%9}, {%0,%1,%2,%3};"
        : "+f"(c[0]), "+f"(c[1]), "+f"(c[2]), "+f"(c[3])
        : "r"(a[0]), "r"(a[1]), "r"(a[2]), "r"(a[3]), "r"(b[0]), "r"(b[1]));
}

__device__ __forceinline__ void cp16(uint32_t dst, const float* src) {
    asm volatile("cp.async.ca.shared.global [%0], [%1], 16;" :: "r"(dst), "l"(src));
}
__device__ __forceinline__ void cp_commit() { asm volatile("cp.async.commit_group;"); }

// ---------------- CSR build ----------------
__global__ void k_zero_cnt() {
    int i = blockIdx.x * blockDim.x + threadIdx.x;
    if (i < NN) { g_cnt[0][i] = 0; g_cnt[1][i] = 0; }
}

__global__ void k_hist2(const int* __restrict__ d0, const int* __restrict__ d1) {
    int et = blockIdx.y;
    const int* dst = et ? d1 : d0;
    int i = blockIdx.x * blockDim.x + threadIdx.x;
    if (i < NE) atomicAdd(&g_cnt[et][dst[i]], 1);
}

__global__ void k_scan1() {
    int et = blockIdx.y;
    __shared__ int s[1024];
    int i = blockIdx.x * 1024 + threadIdx.x;
    int v = (i < NN) ? g_cnt[et][i] : 0;
    s[threadIdx.x] = v;
    __syncthreads();
    for (int o = 1; o < 1024; o <<= 1) {
        int t = (threadIdx.x >= (unsigned)o) ? s[threadIdx.x - o] : 0;
        __syncthreads();
        s[threadIdx.x] += t;
        __syncthreads();
    }
    if (i < NN) g_rowptr[et][i + 1] = s[threadIdx.x];
    if (threadIdx.x == 1023) g_bsums[et][blockIdx.x] = s[1023];
    if (i == 0) g_rowptr[et][0] = 0;
}

__global__ void k_scan2(int nb) {
    if (threadIdx.x == 0) {
        for (int et = 0; et < 2; et++) {
            int acc = 0;
            for (int i = 0; i < nb; i++) { int t = g_bsums[et][i]; g_bsums[et][i] = acc; acc += t; }
        }
    }
}

__global__ void k_scan3() {
    int et = blockIdx.y;
    int i = blockIdx.x * 1024 + threadIdx.x;
    if (i < NN) {
        int v = g_rowptr[et][i + 1] + g_bsums[et][blockIdx.x];
        g_rowptr[et][i + 1] = v;
        g_cursor[et][i + 1] = v;
    }
    if (i == 0) g_cursor[et][0] = 0;
}

__global__ void k_fill2(const int* __restrict__ s0, const int* __restrict__ d0,
                        const int* __restrict__ s1, const int* __restrict__ d1) {
    int et = blockIdx.y;
    const int* src = et ? s1 : s0;
    const int* dst = et ? d1 : d0;
    int i = blockIdx.x * blockDim.x + threadIdx.x;
    if (i < NE) {
        int d = dst[i];
        int pz = atomicAdd(&g_cursor[et][d], 1);
        g_colv[et][pz] = src[i];
    }
}

// ---------------- merged mean aggregation (one warp per dst node) ----------------
__global__ void __launch_bounds__(256) k_agg2(int ha, int hb) {
    int et = blockIdx.y;
    const float* __restrict__ h = pick(et == 0 ? ha : hb);
    float* __restrict__ outp = pick(et == 0 ? 4 : 5);
    int gw = (blockIdx.x * 256 + threadIdx.x) >> 5;
    int lane = threadIdx.x & 31;
    if (gw >= NN) return;
    int beg = g_rowptr[et][gw], end = g_rowptr[et][gw + 1];
    const float4* __restrict__ h4 = (const float4*)h;
    float4 a = make_float4(0.f, 0.f, 0.f, 0.f);
    int e = beg;
    for (; e + 4 <= end; e += 4) {
        int s0 = g_colv[et][e], s1 = g_colv[et][e + 1];
        int s2 = g_colv[et][e + 2], s3 = g_colv[et][e + 3];
        float4 v0 = h4[s0 * 32 + lane];
        float4 v1 = h4[s1 * 32 + lane];
        float4 v2 = h4[s2 * 32 + lane];
        float4 v3 = h4[s3 * 32 + lane];
        a.x += (v0.x + v1.x) + (v2.x + v3.x);
        a.y += (v0.y + v1.y) + (v2.y + v3.y);
        a.z += (v0.z + v1.z) + (v2.z + v3.z);
        a.w += (v0.w + v1.w) + (v2.w + v3.w);
    }
    for (; e < end; e++) {
        int s0 = g_colv[et][e];
        float4 v = h4[s0 * 32 + lane];
        a.x += v.x; a.y += v.y; a.z += v.z; a.w += v.w;
    }
    float invc = 1.0f / fmaxf((float)(end - beg), 1.0f);
    ((float4*)outp)[gw * 32 + lane] = make_float4(a.x * invc, a.y * invc, a.z * invc, a.w * invc);
}

// ---------------- GEMM param set ----------------
struct GP {
    const float* A1p;   // external A (encoders); else pick(a1)
    const float* W1; const float* W2;
    const float* bias;
    const float* bng; const float* bnb; const float* bnm; const float* bnv;
    int a1, a2, res, out;
};

// ---------------- tensor-core GEMM, cp.async double-buffered ----------------
// MODE 0: out = relu(A1@W1 + bias)                      (K=128, N=NW)
// MODE 2: m = rownorm(A1@W1 + A2@W2 + bias); out = relu(bn(m + res))   (K=256 virt, N=128)
template <int MODE, int NT>
__global__ void __launch_bounds__(256, 2) k_gemm2(GP pa, GP pb) {
    constexpr int NST = (MODE == 0) ? 4 : 8;
    constexpr int NW = NT * 16;
    constexpr int WLD2 = NW + 8;
    constexpr int CPR = NW / 4;          // 16B chunks per W row
    constexpr int WCH = (32 * CPR) / 256;
    constexpr int RJ = 256 / CPR;

    extern __shared__ float sm[];
    float* Ws = sm;                          // [2][32][WLD2]
    float* As = Ws + 2 * 32 * WLD2;          // [2][128][ALD]
    float* red = As + 2 * 128 * ALD;         // [128][2]

    GP P = (blockIdx.y == 0) ? pa : pb;
    const float* A1 = (P.a1 >= 0) ? pick(P.a1) : P.A1p;
    const float* A2 = (MODE == 2) ? pick(P.a2) : nullptr;
    const float* res = (MODE == 2) ? pick(P.res) : nullptr;
    float* out = pick(P.out);

    int tid = threadIdx.x;
    int lane = tid & 31, w = tid >> 5;
    int wm = w & 3, wn = w >> 2;
    int p = lane >> 2, q = lane & 3;

    uint32_t ws_u = (uint32_t)__cvta_generic_to_shared(Ws);
    uint32_t as_u = (uint32_t)__cvta_generic_to_shared(As);

    int rowbase = blockIdx.x * TILE_M;
    int arow = tid >> 3;
    int ac4 = (tid & 7) << 2;
    int garow[4];
#pragma unroll
    for (int j = 0; j < 4; j++) {
        int r = rowbase + arow + 32 * j;
        garow[j] = (r < NN) ? r : (NN - 1);
    }
    int wrow0 = tid / CPR;
    int wc4 = (tid % CPR) * 4;

    auto stage = [&](int buf, int s) {
        const float* Asrc = (MODE == 2 && s >= 4) ? A2 : A1;
        int ks = (s & 3) * 32;
#pragma unroll
        for (int j = 0; j < 4; j++) {
            uint32_t d = as_u + (uint32_t)((buf * 128 + arow + 32 * j) * ALD + ac4) * 4u;
            cp16(d, Asrc + (size_t)garow[j] * H + ks + ac4);
        }
#pragma unroll
        for (int j = 0; j < WCH; j++) {
            int row = wrow0 + RJ * j;
            int kw = s * 32 + row;
            const float* wsrc = (MODE == 2 && kw >= 128)
                                    ? (P.W2 + (size_t)(kw - 128) * NW + wc4)
                                    : (P.W1 + (size_t)kw * NW + wc4);
            uint32_t d = ws_u + (uint32_t)((buf * 32 + row) * WLD2 + wc4) * 4u;
            cp16(d, wsrc);
        }
    };

    float acc[2][NT][4];
#pragma unroll
    for (int mt = 0; mt < 2; mt++)
#pragma unroll
        for (int nt = 0; nt < NT; nt++)
#pragma unroll
            for (int e = 0; e < 4; e++) acc[mt][nt][e] = 0.f;

    stage(0, 0);
    cp_commit();

#pragma unroll 1
    for (int s = 0; s < NST; s++) {
        if (s + 1 < NST) {
            stage((s + 1) & 1, s + 1);
            cp_commit();
            asm volatile("cp.async.wait_group 1;");
        } else {
            asm volatile("cp.async.wait_group 0;");
        }
        __syncthreads();
        const float* Asb = As + (s & 1) * 128 * ALD;
        const float* Wsb = Ws + (s & 1) * 32 * WLD2;
#pragma unroll
        for (int cc = 0; cc < 4; cc++) {
            int kl = cc * 8;
            uint32_t a[2][4];
#pragma unroll
            for (int mt = 0; mt < 2; mt++) {
                int r = wm * 32 + mt * 16 + p;
                a[mt][0] = to_tf32_u(Asb[r * ALD + kl + q]);
                a[mt][1] = to_tf32_u(Asb[(r + 8) * ALD + kl + q]);
                a[mt][2] = to_tf32_u(Asb[r * ALD + kl + q + 4]);
                a[mt][3] = to_tf32_u(Asb[(r + 8) * ALD + kl + q + 4]);
            }
            uint32_t b[NT][2];
#pragma unroll
            for (int nt = 0; nt < NT; nt++) {
                int c = wn * (NT * 8) + nt * 8 + p;
                b[nt][0] = to_tf32_u(Wsb[(kl + q) * WLD2 + c]);
                b[nt][1] = to_tf32_u(Wsb[(kl + q + 4) * WLD2 + c]);
            }
#pragma unroll
            for (int mt = 0; mt < 2; mt++)
#pragma unroll
                for (int nt = 0; nt < NT; nt++)
                    mma_tf32(acc[mt][nt], a[mt], b[nt]);
        }
        __syncthreads();
    }

    // ---------------- epilogue ----------------
    float bv[NT][2];
#pragma unroll
    for (int nt = 0; nt < NT; nt++) {
        int c = wn * (NT * 8) + nt * 8 + 2 * q;
        bv[nt][0] = __ldg(&P.bias[c]);
        bv[nt][1] = __ldg(&P.bias[c + 1]);
    }
#pragma unroll
    for (int mt = 0; mt < 2; mt++)
#pragma unroll
        for (int nt = 0; nt < NT; nt++) {
            acc[mt][nt][0] += bv[nt][0];
            acc[mt][nt][1] += bv[nt][1];
            acc[mt][nt][2] += bv[nt][0];
            acc[mt][nt][3] += bv[nt][1];
        }

    if (MODE == 0) {
#pragma unroll
        for (int mt = 0; mt < 2; mt++)
#pragma unroll
            for (int rs = 0; rs < 2; rs++) {
                int r = rowbase + wm * 32 + mt * 16 + p + rs * 8;
                if (r < NN) {
#pragma unroll
                    for (int nt = 0; nt < NT; nt++) {
                        int c = wn * (NT * 8) + nt * 8 + 2 * q;
                        float2 o = make_float2(fmaxf(acc[mt][nt][rs * 2], 0.f),
                                               fmaxf(acc[mt][nt][rs * 2 + 1], 0.f));
                        *(float2*)&out[(size_t)r * NW + c] = o;
                    }
                }
            }
    } else {
        float ss[2][2];
#pragma unroll
        for (int mt = 0; mt < 2; mt++) {
            ss[mt][0] = 0.f; ss[mt][1] = 0.f;
#pragma unroll
            for (int nt = 0; nt < NT; nt++) {
                ss[mt][0] = fmaf(acc[mt][nt][0], acc[mt][nt][0],
                            fmaf(acc[mt][nt][1], acc[mt][nt][1], ss[mt][0]));
                ss[mt][1] = fmaf(acc[mt][nt][2], acc[mt][nt][2],
                            fmaf(acc[mt][nt][3], acc[mt][nt][3], ss[mt][1]));
            }
#pragma unroll
            for (int rs = 0; rs < 2; rs++) {
                ss[mt][rs] += __shfl_xor_sync(0xffffffffu, ss[mt][rs], 1);
                ss[mt][rs] += __shfl_xor_sync(0xffffffffu, ss[mt][rs], 2);
            }
        }
        if (q == 0) {
#pragma unroll
            for (int mt = 0; mt < 2; mt++) {
                red[(wm * 32 + mt * 16 + p) * 2 + wn]     = ss[mt][0];
                red[(wm * 32 + mt * 16 + p + 8) * 2 + wn] = ss[mt][1];
            }
        }
        __syncthreads();

        float scl[NT][2], mh[NT][2], bb[NT][2];
#pragma unroll
        for (int nt = 0; nt < NT; nt++) {
            int c = wn * (NT * 8) + nt * 8 + 2 * q;
            scl[nt][0] = __ldg(&P.bng[c])     * rsqrtf(__ldg(&P.bnv[c]) + 1e-5f);
            scl[nt][1] = __ldg(&P.bng[c + 1]) * rsqrtf(__ldg(&P.bnv[c + 1]) + 1e-5f);
            mh[nt][0] = __ldg(&P.bnm[c]);     mh[nt][1] = __ldg(&P.bnm[c + 1]);
            bb[nt][0] = __ldg(&P.bnb[c]);     bb[nt][1] = __ldg(&P.bnb[c + 1]);
        }
#pragma unroll
        for (int mt = 0; mt < 2; mt++)
#pragma unroll
            for (int rs = 0; rs < 2; rs++) {
                int lr = wm * 32 + mt * 16 + p + rs * 8;
                float tot = red[lr * 2] + red[lr * 2 + 1];
                float inv = 1.0f / fmaxf(sqrtf(tot), 1e-12f);
                int r = rowbase + lr;
                if (r < NN) {
#pragma unroll
                    for (int nt = 0; nt < NT; nt++) {
                        int c = wn * (NT * 8) + nt * 8 + 2 * q;
                        float2 h = *(const float2*)&res[(size_t)r * H + c];
                        float t0 = fmaf(acc[mt][nt][rs * 2], inv, h.x);
                        float t1 = fmaf(acc[mt][nt][rs * 2 + 1], inv, h.y);
                        float2 o = make_float2(
                            fmaxf(fmaf(t0 - mh[nt][0], scl[nt][0], bb[nt][0]), 0.f),
                            fmaxf(fmaf(t1 - mh[nt][1], scl[nt][1], bb[nt][1]), 0.f));
                        *(float2*)&out[(size_t)r * H + c] = o;
                    }
                }
            }
    }
}

// ---------------- classifier stage 2: out = hid@W2 + b2 ----------------
__global__ void __launch_bounds__(256) k_cls2(const float* __restrict__ W2,
                                              const float* __restrict__ b2,
                                              float* __restrict__ out) {
    __shared__ float W2s[HMID * OUTC];
    __shared__ float b2s[OUTC];
    int tid = threadIdx.x;
#pragma unroll
    for (int j = 0; j < 8; j++) W2s[tid + 256 * j] = W2[tid + 256 * j];
    if (tid < OUTC) b2s[tid] = b2[tid];
    __syncthreads();

    int r = blockIdx.x * 256 + tid;
    if (r >= NN) return;
    const float* hid = pick(4) + (size_t)r * HMID;

    float acc[OUTC];
#pragma unroll
    for (int c = 0; c < OUTC; c++) acc[c] = b2s[c];
#pragma unroll
    for (int k4 = 0; k4 < HMID / 4; k4++) {
        float4 a = *(const float4*)(hid + k4 * 4);
        float av[4] = {a.x, a.y, a.z, a.w};
#pragma unroll
        for (int kk = 0; kk < 4; kk++) {
            const float* wr = &W2s[(k4 * 4 + kk) * OUTC];
#pragma unroll
            for (int c = 0; c < OUTC; c++) acc[c] = fmaf(av[kk], wr[c], acc[c]);
        }
    }
#pragma unroll
    for (int c4 = 0; c4 < OUTC / 4; c4++)
        *(float4*)&out[(size_t)r * OUTC + c4 * 4] =
            make_float4(acc[c4 * 4], acc[c4 * 4 + 1], acc[c4 * 4 + 2], acc[c4 * 4 + 3]);
}

// ---------------- launch ----------------
extern "C" void kernel_launch(void* const* d_in, const int* in_sizes, int n_in,
                              void* d_out, int out_size) {
    const float* x_user  = (const float*)d_in[0];
    const float* x_item  = (const float*)d_in[1];
    const float* enc_W_u = (const float*)d_in[2];
    const float* enc_b_u = (const float*)d_in[3];
    const float* enc_W_i = (const float*)d_in[4];
    const float* enc_b_i = (const float*)d_in[5];
    const float* Wl_ui = (const float*)d_in[6];
    const float* bl_ui = (const float*)d_in[7];
    const float* Wr_ui = (const float*)d_in[8];
    const float* Wl_iu = (const float*)d_in[9];
    const float* bl_iu = (const float*)d_in[10];
    const float* Wr_iu = (const float*)d_in[11];
    const float* bng_u = (const float*)d_in[12];
    const float* bnb_u = (const float*)d_in[13];
    const float* bnm_u = (const float*)d_in[14];
    const float* bnv_u = (const float*)d_in[15];
    const float* bng_i = (const float*)d_in[16];
    const float* bnb_i = (const float*)d_in[17];
    const float* bnm_i = (const float*)d_in[18];
    const float* bnv_i = (const float*)d_in[19];
    const float* cW1 = (const float*)d_in[20];
    const float* cb1 = (const float*)d_in[21];
    const float* cW2 = (const float*)d_in[22];
    const float* cb2 = (const float*)d_in[23];
    const int* ei_ui = (const int*)d_in[24];
    const int* ei_iu = (const int*)d_in[25];
    float* outp = (float*)d_out;

    const int SMEM_N8 = (2 * 32 * 136 + 2 * 128 * ALD + 256) * 4;  // 72,704
    const int SMEM_N4 = (2 * 32 * 72  + 2 * 128 * ALD + 256) * 4;  // 56,320

    cudaFuncSetAttribute(k_gemm2<0, 8>, cudaFuncAttributeMaxDynamicSharedMemorySize, SMEM_N8);
    cudaFuncSetAttribute(k_gemm2<2, 8>, cudaFuncAttributeMaxDynamicSharedMemorySize, SMEM_N8);
    cudaFuncSetAttribute(k_gemm2<0, 4>, cudaFuncAttributeMaxDynamicSharedMemorySize, SMEM_N4);

    const int GEMM_GRID = (NN + TILE_M - 1) / TILE_M;   // 782
    const int EB = (NE + 255) / 256;
    const int NB = (NN + 255) / 256;
    const int SB = (NN + 1023) / 1024;

    // ---- CSR (both edge types via blockIdx.y) ----
    k_zero_cnt<<<NB, 256>>>();
    k_hist2<<<dim3(EB, 2), 256>>>(ei_ui + NE, ei_iu + NE);
    k_scan1<<<dim3(SB, 2), 1024>>>();
    k_scan2<<<1, 32>>>(SB);
    k_scan3<<<dim3(SB, 2), 1024>>>();
    k_fill2<<<dim3(EB, 2), 256>>>(ei_ui, ei_ui + NE, ei_iu, ei_iu + NE);

    GP z{}; // zero template

    // ---- encoders (merged): h_u -> buf0, h_i -> buf2 ----
    {
        GP pa = z, pb = z;
        pa.A1p = x_user; pa.W1 = enc_W_u; pa.bias = enc_b_u; pa.a1 = -1; pa.out = 0;
        pb.A1p = x_item; pb.W1 = enc_W_i; pb.bias = enc_b_i; pb.a1 = -1; pb.out = 2;
        k_gemm2<0, 8><<<dim3(GEMM_GRID, 2), 256, SMEM_N8>>>(pa, pb);
    }

    for (int l = 0; l < NL; l++) {
        int hu_cur = l & 1, hu_next = (l + 1) & 1;
        int hi_cur = 2 + (l & 1), hi_next = 2 + ((l + 1) & 1);

        // aggA = mean_ui(h_u) -> buf4 ; aggB = mean_iu(h_i) -> buf5
        k_agg2<<<dim3(NN / 8, 2), 256>>>(hu_cur, hi_cur);

        GP pa = z, pb = z;
        // user update: m_user = rownorm(aggB@Wl_iu + h_i@Wr_iu + b); hu_next = relu(bn_u(m_user + hu_cur))
        pa.a1 = 5; pa.a2 = hi_cur; pa.res = hu_cur; pa.out = hu_next;
        pa.W1 = Wl_iu + (size_t)l * H * H; pa.W2 = Wr_iu + (size_t)l * H * H;
        pa.bias = bl_iu + (size_t)l * H;
        pa.bng = bng_u + (size_t)l * H; pa.bnb = bnb_u + (size_t)l * H;
        pa.bnm = bnm_u + (size_t)l * H; pa.bnv = bnv_u + (size_t)l * H;
        // item update: m_item = rownorm(aggA@Wl_ui + h_u@Wr_ui + b); hi_next = relu(bn_i(m_item + hi_cur))
        pb.a1 = 4; pb.a2 = hu_cur; pb.res = hi_cur; pb.out = hi_next;
        pb.W1 = Wl_ui + (size_t)l * H * H; pb.W2 = Wr_ui + (size_t)l * H * H;
        pb.bias = bl_ui + (size_t)l * H;
        pb.bng = bng_i + (size_t)l * H; pb.bnb = bnb_i + (size_t)l * H;
        pb.bnm = bnm_i + (size_t)l * H; pb.bnv = bnv_i + (size_t)l * H;

        k_gemm2<2, 8><<<dim3(GEMM_GRID, 2), 256, SMEM_N8>>>(pa, pb);
    }

    // ---- classifier: hid = relu(h_u@W1 + b1) -> buf4 (stride 64); out = hid@W2 + b2 ----
    {
        GP pc = z;
        pc.a1 = (NL & 1);           // final h_u buffer
        pc.W1 = cW1; pc.bias = cb1; pc.out = 4;
        k_gemm2<0, 4><<<dim3(GEMM_GRID, 1), 256, SMEM_N4>>>(pc, pc);
        k_cls2<<<NB, 256>>>(cW2, cb2, outp);
    }
}